// round 11
// baseline (speedup 1.0000x reference)
#include <cuda_runtime.h>

// RankCoxHazardLoss — B=512 rows, N=256. Sort-based, role-split:
// 1024 CTAs, 2 per row. role 0 computes the Cox term (scan + survival
// product), role 1 computes the ranking term (prefix violation sums).
// The terms only meet at the final scalar, so no cross-CTA traffic.
// Last CTA (of 1024) reduces the per-row partials to the scalar.

#define EPSF 1e-7f
static constexpr int BB = 512;
static constexpr int NN = 256;

__device__ float g_row_cox[BB];
__device__ float g_row_vb[BB];
__device__ float g_row_rank[BB];
__device__ unsigned int g_done = 0;

__device__ __forceinline__ unsigned long long pack2(float a, float b) {
    unsigned long long r;
    asm("mov.b64 %0, {%1, %2};" : "=l"(r) : "f"(a), "f"(b));
    return r;
}
__device__ __forceinline__ unsigned long long fma2(
    unsigned long long a, unsigned long long b, unsigned long long c) {
    unsigned long long d;
    asm("fma.rn.f32x2 %0, %1, %2, %3;" : "=l"(d) : "l"(a), "l"(b), "l"(c));
    return d;
}
__device__ __forceinline__ unsigned long long mul2(
    unsigned long long a, unsigned long long b) {
    unsigned long long d;
    asm("mul.rn.f32x2 %0, %1, %2;" : "=l"(d) : "l"(a), "l"(b));
    return d;
}
__device__ __forceinline__ void unpack2(unsigned long long v, float& lo, float& hi) {
    asm("mov.b64 {%0, %1}, %2;" : "=f"(lo), "=f"(hi) : "l"(v));
}

__global__ __launch_bounds__(NN) void fused_kernel(
    const float* __restrict__ pred,
    const float* __restrict__ target,
    const void*  __restrict__ validp,
    float*       __restrict__ out)
{
    __shared__ __align__(16) unsigned int s_key[NN];  // sorted runs (32/warp)
    __shared__ float s_p[NN];                  // pred by item index
    __shared__ float s_tm[NN];                 // masked time by item index
    __shared__ __align__(16) float s_e2[NN];   // exp(pred), sorted
    __shared__ __align__(16) float s_x2[NN];   // role0: time | role1: Z, sorted
    __shared__ float s_w0[8], s_w1[8];
    __shared__ int   s_vc[8];
    __shared__ unsigned int s_islast;

    const int tid  = threadIdx.x;
    const int lane = tid & 31;
    const int wid  = tid >> 5;
    const int b    = blockIdx.x >> 1;
    const int role = blockIdx.x & 1;      // 0 = cox, 1 = rank
    const int idx  = b * NN + tid;

    // ---- valid_mask dtype detection: warp-local, element SIZE only ----
    const unsigned int w = ((const unsigned int*)validp)[tid];
    unsigned int pat = 0u;
    if ((w == 0x3F803F80u) || (w == 0x00003F80u)) pat |= 1u;          // 2-byte
    else if ((w & 0xFFFFFF00u) != 0u && w != 0x3F800000u) pat |= 4u;  // 1-byte
    const unsigned int wpat = __reduce_or_sync(0xffffffffu, pat);
    bool v_i;
    if (wpat & 1u)      v_i = ((const unsigned short*)validp)[idx] != 0;
    else if (wpat & 4u) v_i = ((const unsigned char*)validp)[idx] != 0;
    else                v_i = ((const unsigned int*)validp)[idx] != 0u;

    const float p_i  = pred[idx];
    const float t_i  = target[idx];
    const float tm_i = v_i ? t_i : -1.0f;

    // unique sortable key: ordered float bits, low 8 bits = item index
    unsigned int u = __float_as_uint(tm_i);
    u ^= (unsigned int)((int)u >> 31) | 0x80000000u;
    const unsigned int key = (u & 0xFFFFFF00u) | (unsigned int)tid;

    s_p[tid]  = p_i;
    s_tm[tid] = tm_i;
    const unsigned int bal = __ballot_sync(0xffffffffu, v_i);
    if (lane == 0) s_vc[wid] = __popc(bal);

    // ---- warp bitonic sort (ascending by lane) of the 32 keys ----
    unsigned int v = key;
    #pragma unroll
    for (int kk = 2; kk <= 32; kk <<= 1) {
        #pragma unroll
        for (int j = kk >> 1; j > 0; j >>= 1) {
            const unsigned int o = __shfl_xor_sync(0xffffffffu, v, j);
            const bool takeMin = (((lane & kk) == 0) == ((lane & j) == 0));
            v = takeMin ? umin(v, o) : umax(v, o);
        }
    }
    s_key[wid * 32 + lane] = v;
    __syncthreads();

    // ---- global rank of v = sum of lower_bounds over the 8 sorted runs ----
    int rank = 0;
    #pragma unroll
    for (int w2 = 0; w2 < 8; w2++) {
        const unsigned int* run = s_key + w2 * 32;
        int c = 0;
        if (run[c + 15] < v) c += 16;
        if (run[c + 7]  < v) c += 8;
        if (run[c + 3]  < v) c += 4;
        if (run[c + 1]  < v) c += 2;
        if (run[c]      < v) c += 1;
        if (run[c]      < v) c += 1;   // fixup (count may be 32)
        rank += c;
    }

    // ---- holder-thread scatter: item i2 = v & 0xFF goes to slot `rank` ----
    {
        const int i2    = (int)(v & 0xFFu);
        const float p2  = s_p[i2];
        const float tm2 = s_tm[i2];
        const float e2  = __expf(p2);
        s_e2[rank] = e2;
        s_x2[rank] = role ? ((tm2 < 0.0f) ? 0.0f : __frcp_rn(e2))  // Z
                          : tm2;                                    // time
    }
    int vcnt = 0;
    #pragma unroll
    for (int k2 = 0; k2 < 8; k2++) vcnt += s_vc[k2];
    const int ninv = NN - vcnt;
    __syncthreads();

    const int   k   = tid;            // sorted slot owned by this thread
    const float E_k = s_e2[k];
    const bool  valid_k = (k >= ninv);
    const int   qb = k >> 2;          // boundary quad index
    const int   kc = k & 3;           // position within boundary quad
    const float4* e4 = (const float4*)s_e2;

    float result = 0.0f;              // role 0: loss_k ; role 1: rankc_k

    if (role == 0) {
        // ===== COX =====
        const float T_k  = s_x2[k];
        const float bmax = s_x2[NN - 1];

        // den_k = suffix sum of E over [k, 255]
        float sfx = E_k;
        #pragma unroll
        for (int o = 1; o < 32; o <<= 1) {
            const float t = __shfl_down_sync(0xffffffffu, sfx, o);
            if (lane + o < 32) sfx += t;
        }
        if (lane == 0) s_w0[wid] = sfx;
        __syncthreads();
        float den = sfx;
        #pragma unroll
        for (int k2 = 7; k2 > 0; k2--) if (k2 > wid) den += s_w0[k2];
        const float invden = 1.0f / den;

        // survival product over strict suffix j>k
        const float c1c = 1.0f + EPSF;
        float pdx = 1.0f;
        {   // boundary quad: pairs j = 4*qb + c with c > kc
            const float4 E = e4[qb];
            if (0 > kc) pdx *= fmaf(-E.x, invden, c1c);
            if (1 > kc) pdx *= fmaf(-E.y, invden, c1c);
            if (2 > kc) pdx *= fmaf(-E.z, invden, c1c);
            if (3 > kc) pdx *= fmaf(-E.w, invden, c1c);
        }
        const unsigned long long ninv2 = pack2(-invden, -invden);
        const unsigned long long c1c2  = pack2(c1c, c1c);
        unsigned long long pdA = pack2(1.0f, 1.0f);
        unsigned long long pdB = pdA;
        const ulonglong2* e8 = (const ulonglong2*)s_e2;
        #pragma unroll 4
        for (int q = qb + 1; q < NN / 4; q++) {
            const ulonglong2 E2 = e8[q];
            pdA = mul2(pdA, fma2(E2.x, ninv2, c1c2));
            pdB = mul2(pdB, fma2(E2.y, ninv2, c1c2));
        }
        float a0, a1, b0, b1;
        unpack2(pdA, a0, a1);
        unpack2(pdB, b0, b1);
        const float prod = pdx * ((a0 * a1) * (b0 * b1));

        const bool elim = valid_k && (T_k > 0.0f) && (T_k < bmax);
        if (elim) result = __logf(den / (E_k * prod));
    } else {
        // ===== RANK =====
        const float4* z4 = (const float4*)s_x2;
        float rsA = 0.0f, rsB = 0.0f;
        #pragma unroll 4
        for (int q = 0; q < qb; q++) {
            const float4 E = e4[q];
            const float4 Z = z4[q];
            if (E.x < E_k) rsA += Z.x;
            if (E.y < E_k) rsB += Z.y;
            if (E.z < E_k) rsA += Z.z;
            if (E.w < E_k) rsB += Z.w;
        }
        {   // boundary quad: pairs j = 4*qb + c with c < kc
            const float4 E = e4[qb];
            const float4 Z = z4[qb];
            if (0 < kc && E.x < E_k) rsA += Z.x;
            if (1 < kc && E.y < E_k) rsB += Z.y;
            if (2 < kc && E.z < E_k) rsA += Z.z;
        }
        if (valid_k) result = E_k * (rsA + rsB);
    }

    // ---- block reduce result ----
    #pragma unroll
    for (int o = 16; o; o >>= 1)
        result += __shfl_xor_sync(0xffffffffu, result, o);
    __syncthreads();                     // protect s_w1 (role0 used s_w0)
    if (lane == 0) s_w1[wid] = result;
    __syncthreads();
    if (tid == 0) {
        float tot = 0.0f;
        #pragma unroll
        for (int k2 = 0; k2 < 8; k2++) tot += s_w1[k2];
        const float vb = (vcnt >= 2) ? 1.0f : 0.0f;
        if (role == 0) {
            g_row_cox[b] = vb * tot;
            g_row_vb[b]  = vb;
        } else {
            const float fv = (float)vcnt;
            const float npairs = 0.5f * fv * (fv - 1.0f);   // C(vcnt,2)
            g_row_rank[b] = tot / fmaxf(npairs, 1.0f);
        }
        __threadfence();
        const unsigned int t = atomicAdd(&g_done, 1u);
        s_islast = (t == (unsigned int)(2 * BB - 1)) ? 1u : 0u;
    }
    __syncthreads();

    // ---- last CTA: final scalar reduction over 512 rows ----
    if (s_islast) {
        float c  = g_row_cox[tid]  + g_row_cox[tid + NN];
        float v2 = g_row_vb[tid]   + g_row_vb[tid + NN];
        float r  = g_row_rank[tid] + g_row_rank[tid + NN];
        #pragma unroll
        for (int o = 16; o; o >>= 1) {
            c  += __shfl_xor_sync(0xffffffffu, c, o);
            v2 += __shfl_xor_sync(0xffffffffu, v2, o);
            r  += __shfl_xor_sync(0xffffffffu, r, o);
        }
        __syncthreads();
        if (lane == 0) { s_w0[wid] = c; s_w1[wid] = v2; ((float*)s_vc)[wid] = r; }
        __syncthreads();
        if (tid == 0) {
            float C = 0.0f, V = 0.0f, R = 0.0f;
            #pragma unroll
            for (int k2 = 0; k2 < 8; k2++) {
                C += s_w0[k2]; V += s_w1[k2]; R += ((float*)s_vc)[k2];
            }
            out[0] = C / fmaxf(V, 1.0f) + R * (1.0f / (float)BB);
            g_done = 0;   // reset for next graph replay
        }
    }
}

extern "C" void kernel_launch(void* const* d_in, const int* in_sizes, int n_in,
                              void* d_out, int out_size)
{
    const float* pred   = (const float*)d_in[0];
    const float* target = (const float*)d_in[1];
    const void*  valid  = (const void*)d_in[2];
    float*       out    = (float*)d_out;

    fused_kernel<<<2 * BB, NN>>>(pred, target, valid, out);
}

// round 12
// speedup vs baseline: 1.0215x; 1.0215x over previous
#include <cuda_runtime.h>

// RankCoxHazardLoss — B=512 rows, N=256. Sort-based, intra-CTA role split:
// 512 CTAs x 512 threads. Warps 0-7 (role 0) run the preamble (bitonic sort,
// rank, scatter) then compute the Cox term (suffix scan + survival product).
// Warps 8-15 (role 1) concurrently compute the ranking term (prefix
// violation sums). Terms meet only at the final scalar.

#define EPSF 1e-7f
static constexpr int BB  = 512;
static constexpr int NN  = 256;
static constexpr int TPB = 512;

__device__ float g_row_cox[BB];
__device__ float g_row_vb[BB];
__device__ float g_row_rank[BB];
__device__ unsigned int g_done = 0;

__device__ __forceinline__ unsigned long long pack2(float a, float b) {
    unsigned long long r;
    asm("mov.b64 %0, {%1, %2};" : "=l"(r) : "f"(a), "f"(b));
    return r;
}
__device__ __forceinline__ unsigned long long fma2(
    unsigned long long a, unsigned long long b, unsigned long long c) {
    unsigned long long d;
    asm("fma.rn.f32x2 %0, %1, %2, %3;" : "=l"(d) : "l"(a), "l"(b), "l"(c));
    return d;
}
__device__ __forceinline__ unsigned long long mul2(
    unsigned long long a, unsigned long long b) {
    unsigned long long d;
    asm("mul.rn.f32x2 %0, %1, %2;" : "=l"(d) : "l"(a), "l"(b));
    return d;
}
__device__ __forceinline__ void unpack2(unsigned long long v, float& lo, float& hi) {
    asm("mov.b64 {%0, %1}, %2;" : "=f"(lo), "=f"(hi) : "l"(v));
}

__global__ __launch_bounds__(TPB) void fused_kernel(
    const float* __restrict__ pred,
    const float* __restrict__ target,
    const void*  __restrict__ validp,
    float*       __restrict__ out)
{
    __shared__ __align__(16) unsigned int s_key[NN];  // sorted runs (32/warp)
    __shared__ float s_p[NN];                  // pred by item index
    __shared__ float s_tm[NN];                 // masked time by item index
    __shared__ __align__(16) float s_e2[NN];   // exp(pred), sorted
    __shared__ __align__(16) float s_rz[NN];   // valid ? 1/exp(pred) : 0, sorted
    __shared__ __align__(16) float s_t2[NN];   // masked time, sorted
    __shared__ float s_w0[8];                  // scan warp totals (cox half)
    __shared__ float s_r[16];                  // per-warp reduced results
    __shared__ int   s_vc[8];
    __shared__ unsigned int s_islast;

    const int tid  = threadIdx.x;
    const int k    = tid & (NN - 1);   // item / sorted slot
    const int role = tid >> 8;         // 0 = cox (+preamble), 1 = rank
    const int lane = tid & 31;
    const int wid  = tid >> 5;         // 0..15
    const int b    = blockIdx.x;
    const int idx  = b * NN + k;

    // ================= preamble: role 0 only =================
    if (role == 0) {
        // valid_mask dtype detection: warp-local, element SIZE only
        const unsigned int w = ((const unsigned int*)validp)[k];
        unsigned int pat = 0u;
        if ((w == 0x3F803F80u) || (w == 0x00003F80u)) pat |= 1u;          // 2B
        else if ((w & 0xFFFFFF00u) != 0u && w != 0x3F800000u) pat |= 4u;  // 1B
        const unsigned int wpat = __reduce_or_sync(0xffffffffu, pat);
        bool v_i;
        if (wpat & 1u)      v_i = ((const unsigned short*)validp)[idx] != 0;
        else if (wpat & 4u) v_i = ((const unsigned char*)validp)[idx] != 0;
        else                v_i = ((const unsigned int*)validp)[idx] != 0u;

        const float p_i  = pred[idx];
        const float t_i  = target[idx];
        const float tm_i = v_i ? t_i : -1.0f;

        // unique sortable key: ordered float bits, low 8 bits = item index
        unsigned int u = __float_as_uint(tm_i);
        u ^= (unsigned int)((int)u >> 31) | 0x80000000u;
        const unsigned int key = (u & 0xFFFFFF00u) | (unsigned int)k;

        s_p[k]  = p_i;
        s_tm[k] = tm_i;
        const unsigned int bal = __ballot_sync(0xffffffffu, v_i);
        if (lane == 0) s_vc[wid] = __popc(bal);

        // warp bitonic sort (ascending by lane) of the 32 keys
        unsigned int v = key;
        #pragma unroll
        for (int kk = 2; kk <= 32; kk <<= 1) {
            #pragma unroll
            for (int j = kk >> 1; j > 0; j >>= 1) {
                const unsigned int o = __shfl_xor_sync(0xffffffffu, v, j);
                const bool takeMin = (((lane & kk) == 0) == ((lane & j) == 0));
                v = takeMin ? umin(v, o) : umax(v, o);
            }
        }
        s_key[wid * 32 + lane] = v;
        __syncthreads();                               // B1

        // global rank of v = sum of lower_bounds over the 8 sorted runs
        int rank = 0;
        #pragma unroll
        for (int w2 = 0; w2 < 8; w2++) {
            const unsigned int* run = s_key + w2 * 32;
            int c = 0;
            if (run[c + 15] < v) c += 16;
            if (run[c + 7]  < v) c += 8;
            if (run[c + 3]  < v) c += 4;
            if (run[c + 1]  < v) c += 2;
            if (run[c]      < v) c += 1;
            if (run[c]      < v) c += 1;   // fixup (count may be 32)
            rank += c;
        }
        // holder-thread scatter: item i2 = v & 0xFF goes to slot `rank`
        const int i2    = (int)(v & 0xFFu);
        const float p2  = s_p[i2];
        const float tm2 = s_tm[i2];
        const float e2  = __expf(p2);
        s_e2[rank] = e2;
        s_rz[rank] = (tm2 < 0.0f) ? 0.0f : __frcp_rn(e2);
        s_t2[rank] = tm2;
    } else {
        __syncthreads();                               // B1 (idle half)
    }
    __syncthreads();                                   // B2

    int vcnt = 0;
    #pragma unroll
    for (int k2 = 0; k2 < 8; k2++) vcnt += s_vc[k2];
    const int ninv = NN - vcnt;

    const float E_k = s_e2[k];
    const bool  valid_k = (k >= ninv);
    const int   qb = k >> 2;           // boundary quad index
    const int   kc = k & 3;            // position within boundary quad
    const float4* e4 = (const float4*)s_e2;

    float result = 0.0f;               // role 0: loss_k ; role 1: rankc_k

    if (role == 0) {
        // ===== COX: suffix scan + survival product =====
        float sfx = E_k;
        #pragma unroll
        for (int o = 1; o < 32; o <<= 1) {
            const float t = __shfl_down_sync(0xffffffffu, sfx, o);
            if (lane + o < 32) sfx += t;
        }
        if (lane == 0) s_w0[wid] = sfx;
        asm volatile("bar.sync 1, 256;" ::: "memory");  // cox-half barrier
        float den = sfx;
        #pragma unroll
        for (int k2 = 7; k2 > 0; k2--) if (k2 > wid) den += s_w0[k2];
        const float invden = 1.0f / den;

        const float c1c = 1.0f + EPSF;
        float pdx = 1.0f;
        {   // boundary quad: pairs j = 4*qb + c with c > kc
            const float4 E = e4[qb];
            if (0 > kc) pdx *= fmaf(-E.x, invden, c1c);
            if (1 > kc) pdx *= fmaf(-E.y, invden, c1c);
            if (2 > kc) pdx *= fmaf(-E.z, invden, c1c);
            if (3 > kc) pdx *= fmaf(-E.w, invden, c1c);
        }
        const unsigned long long ninv2 = pack2(-invden, -invden);
        const unsigned long long c1c2  = pack2(c1c, c1c);
        unsigned long long pdA = pack2(1.0f, 1.0f);
        unsigned long long pdB = pdA;
        const ulonglong2* e8 = (const ulonglong2*)s_e2;
        #pragma unroll 4
        for (int q = qb + 1; q < NN / 4; q++) {
            const ulonglong2 E2 = e8[q];
            pdA = mul2(pdA, fma2(E2.x, ninv2, c1c2));
            pdB = mul2(pdB, fma2(E2.y, ninv2, c1c2));
        }
        float a0, a1, b0, b1;
        unpack2(pdA, a0, a1);
        unpack2(pdB, b0, b1);
        const float prod = pdx * ((a0 * a1) * (b0 * b1));

        const float T_k  = s_t2[k];
        const float bmax = s_t2[NN - 1];
        const bool elim = valid_k && (T_k > 0.0f) && (T_k < bmax);
        if (elim) result = __logf(den / (E_k * prod));
    } else {
        // ===== RANK: prefix violation sum =====
        const float4* z4 = (const float4*)s_rz;
        float rsA = 0.0f, rsB = 0.0f;
        #pragma unroll 4
        for (int q = 0; q < qb; q++) {
            const float4 E = e4[q];
            const float4 Z = z4[q];
            if (E.x < E_k) rsA += Z.x;
            if (E.y < E_k) rsB += Z.y;
            if (E.z < E_k) rsA += Z.z;
            if (E.w < E_k) rsB += Z.w;
        }
        {   // boundary quad: pairs j = 4*qb + c with c < kc
            const float4 E = e4[qb];
            const float4 Z = z4[qb];
            if (0 < kc && E.x < E_k) rsA += Z.x;
            if (1 < kc && E.y < E_k) rsB += Z.y;
            if (2 < kc && E.z < E_k) rsA += Z.z;
        }
        if (valid_k) result = E_k * (rsA + rsB);
    }

    // ---- per-warp reduce, then combine ----
    #pragma unroll
    for (int o = 16; o; o >>= 1)
        result += __shfl_xor_sync(0xffffffffu, result, o);
    if (lane == 0) s_r[wid] = result;
    __syncthreads();                                   // B3
    if (tid == 0) {
        float tl = 0.0f, tr = 0.0f;
        #pragma unroll
        for (int k2 = 0; k2 < 8; k2++) { tl += s_r[k2]; tr += s_r[k2 + 8]; }
        const float fv = (float)vcnt;
        const float npairs = 0.5f * fv * (fv - 1.0f);   // C(vcnt,2)
        const float vb = (vcnt >= 2) ? 1.0f : 0.0f;
        g_row_cox[b]  = vb * tl;
        g_row_vb[b]   = vb;
        g_row_rank[b] = tr / fmaxf(npairs, 1.0f);
        __threadfence();
        const unsigned int t = atomicAdd(&g_done, 1u);
        s_islast = (t == (unsigned int)(BB - 1)) ? 1u : 0u;
    }
    __syncthreads();                                   // B4

    // ---- last CTA: final scalar reduction over the 512 rows ----
    if (s_islast) {
        float c  = g_row_cox[tid];
        float v2 = g_row_vb[tid];
        float r  = g_row_rank[tid];
        #pragma unroll
        for (int o = 16; o; o >>= 1) {
            c  += __shfl_xor_sync(0xffffffffu, c, o);
            v2 += __shfl_xor_sync(0xffffffffu, v2, o);
            r  += __shfl_xor_sync(0xffffffffu, r, o);
        }
        __syncthreads();
        if (lane == 0) { s_r[wid] = c; s_w0[wid & 7] = 0.0f; }  // placeholder
        // use three arrays properly:
        __syncthreads();
        if (lane == 0) {
            s_r[wid] = c;
            ((float*)s_vc)[wid & 7] = 0.0f;
        }
        __syncthreads();
        // simpler: redo with dedicated shared rows
        __shared__ float s_fc[16], s_fv[16], s_fr[16];
        if (lane == 0) { s_fc[wid] = c; s_fv[wid] = v2; s_fr[wid] = r; }
        __syncthreads();
        if (tid == 0) {
            float C = 0.0f, V = 0.0f, R = 0.0f;
            #pragma unroll
            for (int k2 = 0; k2 < 16; k2++) {
                C += s_fc[k2]; V += s_fv[k2]; R += s_fr[k2];
            }
            out[0] = C / fmaxf(V, 1.0f) + R * (1.0f / (float)BB);
            g_done = 0;   // reset for next graph replay
        }
    }
}

extern "C" void kernel_launch(void* const* d_in, const int* in_sizes, int n_in,
                              void* d_out, int out_size)
{
    const float* pred   = (const float*)d_in[0];
    const float* target = (const float*)d_in[1];
    const void*  valid  = (const void*)d_in[2];
    float*       out    = (float*)d_out;

    fused_kernel<<<BB, TPB>>>(pred, target, valid, out);
}

// round 13
// speedup vs baseline: 1.1011x; 1.0779x over previous
#include <cuda_runtime.h>

// RankCoxHazardLoss — B=512 rows, N=256. Sort-based, 256 thr/row.
// Rank via warp-bitonic sort + 7x binary search (own run = lane); holder
// scatter; warp-local dtype detection; rs loop overlaps scan barrier;
// den = suffix scan; pass2 over strict suffix with packed f32x2.
// Last CTA reduces the per-row partials to the scalar.

#define EPSF 1e-7f
static constexpr int BB = 512;
static constexpr int NN = 256;

__device__ float g_row_cox[BB];
__device__ float g_row_vb[BB];
__device__ float g_row_rank[BB];
__device__ unsigned int g_done = 0;

__device__ __forceinline__ unsigned long long pack2(float a, float b) {
    unsigned long long r;
    asm("mov.b64 %0, {%1, %2};" : "=l"(r) : "f"(a), "f"(b));
    return r;
}
__device__ __forceinline__ unsigned long long fma2(
    unsigned long long a, unsigned long long b, unsigned long long c) {
    unsigned long long d;
    asm("fma.rn.f32x2 %0, %1, %2, %3;" : "=l"(d) : "l"(a), "l"(b), "l"(c));
    return d;
}
__device__ __forceinline__ unsigned long long mul2(
    unsigned long long a, unsigned long long b) {
    unsigned long long d;
    asm("mul.rn.f32x2 %0, %1, %2;" : "=l"(d) : "l"(a), "l"(b));
    return d;
}
__device__ __forceinline__ void unpack2(unsigned long long v, float& lo, float& hi) {
    asm("mov.b64 {%0, %1}, %2;" : "=f"(lo), "=f"(hi) : "l"(v));
}

__global__ __launch_bounds__(NN) void fused_kernel(
    const float* __restrict__ pred,
    const float* __restrict__ target,
    const void*  __restrict__ validp,
    float*       __restrict__ out)
{
    __shared__ __align__(16) unsigned int s_key[NN];  // sorted runs (32/warp)
    __shared__ float s_p[NN];                  // pred by item index
    __shared__ float s_tm[NN];                 // masked time by item index
    __shared__ __align__(16) float s_e2[NN];   // exp(pred), sorted
    __shared__ __align__(16) float s_rz[NN];   // valid ? 1/exp(pred) : 0, sorted
    __shared__ __align__(16) float s_t2[NN];   // masked time, sorted
    __shared__ float s_w0[8], s_w1[8];
    __shared__ int   s_vc[8];
    __shared__ unsigned int s_islast;

    const int tid  = threadIdx.x;
    const int lane = tid & 31;
    const int wid  = tid >> 5;
    const int b    = blockIdx.x;
    const int idx  = b * NN + tid;

    // ---- valid_mask dtype detection: warp-local, element SIZE only ----
    const unsigned int w = ((const unsigned int*)validp)[tid];
    unsigned int pat = 0u;
    if ((w == 0x3F803F80u) || (w == 0x00003F80u)) pat |= 1u;          // 2-byte
    else if ((w & 0xFFFFFF00u) != 0u && w != 0x3F800000u) pat |= 4u;  // 1-byte
    const unsigned int wpat = __reduce_or_sync(0xffffffffu, pat);
    bool v_i;
    if (wpat & 1u)      v_i = ((const unsigned short*)validp)[idx] != 0;
    else if (wpat & 4u) v_i = ((const unsigned char*)validp)[idx] != 0;
    else                v_i = ((const unsigned int*)validp)[idx] != 0u;

    const float p_i  = pred[idx];
    const float t_i  = target[idx];
    const float tm_i = v_i ? t_i : -1.0f;

    // unique sortable key: ordered float bits, low 8 bits = item index
    unsigned int u = __float_as_uint(tm_i);
    u ^= (unsigned int)((int)u >> 31) | 0x80000000u;
    const unsigned int key = (u & 0xFFFFFF00u) | (unsigned int)tid;

    s_p[tid]  = p_i;
    s_tm[tid] = tm_i;
    const unsigned int bal = __ballot_sync(0xffffffffu, v_i);
    if (lane == 0) s_vc[wid] = __popc(bal);

    // ---- warp bitonic sort (ascending by lane) of the 32 keys ----
    unsigned int v = key;
    #pragma unroll
    for (int kk = 2; kk <= 32; kk <<= 1) {
        #pragma unroll
        for (int j = kk >> 1; j > 0; j >>= 1) {
            const unsigned int o = __shfl_xor_sync(0xffffffffu, v, j);
            const bool takeMin = (((lane & kk) == 0) == ((lane & j) == 0));
            v = takeMin ? umin(v, o) : umax(v, o);
        }
    }
    s_key[wid * 32 + lane] = v;
    __syncthreads();                                   // B1

    // ---- global rank of v: own run contributes `lane` (keys unique,
    //      run ascending); 7 other runs via branchless lower_bound.
    //      (w2 == wid) is warp-uniform, so the skip is divergence-free. ----
    int rank = lane;
    #pragma unroll
    for (int w2 = 0; w2 < 8; w2++) {
        if (w2 != wid) {
            const unsigned int* run = s_key + w2 * 32;
            int c = 0;
            if (run[c + 15] < v) c += 16;
            if (run[c + 7]  < v) c += 8;
            if (run[c + 3]  < v) c += 4;
            if (run[c + 1]  < v) c += 2;
            if (run[c]      < v) c += 1;
            if (run[c]      < v) c += 1;   // fixup (count may be 32)
            rank += c;
        }
    }

    // ---- holder-thread scatter: item i2 = v & 0xFF goes to slot `rank` ----
    {
        const int i2    = (int)(v & 0xFFu);
        const float p2  = s_p[i2];
        const float tm2 = s_tm[i2];
        const float e2  = __expf(p2);
        s_e2[rank] = e2;
        s_rz[rank] = (tm2 < 0.0f) ? 0.0f : __frcp_rn(e2);
        s_t2[rank] = tm2;
    }
    int vcnt = 0;
    #pragma unroll
    for (int k2 = 0; k2 < 8; k2++) vcnt += s_vc[k2];
    const int ninv = NN - vcnt;
    __syncthreads();                                   // B2

    const int   k   = tid;            // sorted slot owned by this thread
    const float E_k = s_e2[k];
    const float T_k = s_t2[k];
    const float bmax = s_t2[NN - 1];

    const int qb = k >> 2;       // boundary quad index
    const int kc = k & 3;        // position within boundary quad

    // ---- rank violations over prefix j<k (before scan: overlaps barrier) ----
    const float4* e4 = (const float4*)s_e2;
    const float4* z4 = (const float4*)s_rz;
    float rsA = 0.0f, rsB = 0.0f;
    #pragma unroll 8
    for (int q = 0; q < qb; q++) {
        const float4 E = e4[q];
        const float4 Z = z4[q];
        if (E.x < E_k) rsA += Z.x;
        if (E.y < E_k) rsB += Z.y;
        if (E.z < E_k) rsA += Z.z;
        if (E.w < E_k) rsB += Z.w;
    }
    {   // boundary quad: pairs j = 4*qb + c with c < kc
        const float4 E = e4[qb];
        const float4 Z = z4[qb];
        if (0 < kc && E.x < E_k) rsA += Z.x;
        if (1 < kc && E.y < E_k) rsB += Z.y;
        if (2 < kc && E.z < E_k) rsA += Z.z;
    }
    const float rs = rsA + rsB;

    // ---- den_k = suffix sum of E over [k, 255] ----
    float sfx = E_k;
    #pragma unroll
    for (int o = 1; o < 32; o <<= 1) {
        const float t = __shfl_down_sync(0xffffffffu, sfx, o);
        if (lane + o < 32) sfx += t;
    }
    if (lane == 0) s_w0[wid] = sfx;
    __syncthreads();                                   // B3
    float den = sfx;
    #pragma unroll
    for (int k2 = 7; k2 > 0; k2--) if (k2 > wid) den += s_w0[k2];
    const float invden = 1.0f / den;

    // ---- pass 2: survival product over strict suffix j>k ----
    // term_j = (1+eps) - E_j/den_k  (clamp provably never fires for j>k)
    const float c1c = 1.0f + EPSF;
    float pdx = 1.0f;
    {   // boundary quad: pairs j = 4*qb + c with c > kc
        const float4 E = e4[qb];
        if (0 > kc) pdx *= fmaf(-E.x, invden, c1c);
        if (1 > kc) pdx *= fmaf(-E.y, invden, c1c);
        if (2 > kc) pdx *= fmaf(-E.z, invden, c1c);
        if (3 > kc) pdx *= fmaf(-E.w, invden, c1c);
    }
    const unsigned long long ninv2 = pack2(-invden, -invden);
    const unsigned long long c1c2  = pack2(c1c, c1c);
    unsigned long long pdA = pack2(1.0f, 1.0f);
    unsigned long long pdB = pdA;
    const ulonglong2* e8 = (const ulonglong2*)s_e2;
    #pragma unroll 8
    for (int q = qb + 1; q < NN / 4; q++) {
        const ulonglong2 E2 = e8[q];
        pdA = mul2(pdA, fma2(E2.x, ninv2, c1c2));
        pdB = mul2(pdB, fma2(E2.y, ninv2, c1c2));
    }
    float a0, a1, b0, b1;
    unpack2(pdA, a0, a1);
    unpack2(pdB, b0, b1);
    const float prod = pdx * ((a0 * a1) * (b0 * b1));

    // ---- finalize per sorted slot ----
    const bool valid_k = (k >= ninv);
    const bool elim = valid_k && (T_k > 0.0f) && (T_k < bmax);
    float loss = 0.0f;
    if (elim)
        loss = __logf(den / (E_k * prod));
    float rankc = valid_k ? E_k * rs : 0.0f;

    // ---- block reduce (loss, rankc) ----
    #pragma unroll
    for (int o = 16; o; o >>= 1) {
        loss  += __shfl_xor_sync(0xffffffffu, loss, o);
        rankc += __shfl_xor_sync(0xffffffffu, rankc, o);
    }
    __syncthreads();                                   // B4 (s_w0 reuse)
    if (lane == 0) { s_w0[wid] = loss; s_w1[wid] = rankc; }
    __syncthreads();                                   // B5
    if (tid == 0) {
        float tl = 0.0f, tr = 0.0f;
        #pragma unroll
        for (int k2 = 0; k2 < 8; k2++) { tl += s_w0[k2]; tr += s_w1[k2]; }
        const float fv = (float)vcnt;
        const float npairs = 0.5f * fv * (fv - 1.0f);   // C(vcnt,2)
        const float vb = (vcnt >= 2) ? 1.0f : 0.0f;
        g_row_cox[b]  = vb * tl;
        g_row_vb[b]   = vb;
        g_row_rank[b] = tr / fmaxf(npairs, 1.0f);
        __threadfence();
        const unsigned int t = atomicAdd(&g_done, 1u);
        s_islast = (t == (unsigned int)(BB - 1)) ? 1u : 0u;
    }
    __syncthreads();                                   // B6

    // ---- last block: final scalar reduction over 512 rows ----
    if (s_islast) {
        float c  = g_row_cox[tid]  + g_row_cox[tid + NN];
        float v2 = g_row_vb[tid]   + g_row_vb[tid + NN];
        float r  = g_row_rank[tid] + g_row_rank[tid + NN];
        #pragma unroll
        for (int o = 16; o; o >>= 1) {
            c  += __shfl_xor_sync(0xffffffffu, c, o);
            v2 += __shfl_xor_sync(0xffffffffu, v2, o);
            r  += __shfl_xor_sync(0xffffffffu, r, o);
        }
        __syncthreads();
        if (lane == 0) { s_w0[wid] = c; s_w1[wid] = v2; ((float*)s_vc)[wid] = r; }
        __syncthreads();
        if (tid == 0) {
            float C = 0.0f, V = 0.0f, R = 0.0f;
            #pragma unroll
            for (int k2 = 0; k2 < 8; k2++) {
                C += s_w0[k2]; V += s_w1[k2]; R += ((float*)s_vc)[k2];
            }
            out[0] = C / fmaxf(V, 1.0f) + R * (1.0f / (float)BB);
            g_done = 0;   // reset for next graph replay
        }
    }
}

extern "C" void kernel_launch(void* const* d_in, const int* in_sizes, int n_in,
                              void* d_out, int out_size)
{
    const float* pred   = (const float*)d_in[0];
    const float* target = (const float*)d_in[1];
    const void*  valid  = (const void*)d_in[2];
    float*       out    = (float*)d_out;

    fused_kernel<<<BB, NN>>>(pred, target, valid, out);
}

// round 16
// speedup vs baseline: 1.1223x; 1.0193x over previous
#include <cuda_runtime.h>

// RankCoxHazardLoss — B=512 rows, N=256. Sort-based, 256 thr/row.
// Rank via warp-bitonic sort + 7x binary search (own run contributes `lane`);
// holder scatter; warp-local dtype detection; den = suffix scan; rank
// violations over prefix j<k; pass2 survival product over strict suffix j>k
// with packed f32x2. Last CTA reduces the per-row partials to the scalar.

#define EPSF 1e-7f
static constexpr int BB = 512;
static constexpr int NN = 256;

__device__ float g_row_cox[BB];
__device__ float g_row_vb[BB];
__device__ float g_row_rank[BB];
__device__ unsigned int g_done = 0;

__device__ __forceinline__ unsigned long long pack2(float a, float b) {
    unsigned long long r;
    asm("mov.b64 %0, {%1, %2};" : "=l"(r) : "f"(a), "f"(b));
    return r;
}
__device__ __forceinline__ unsigned long long fma2(
    unsigned long long a, unsigned long long b, unsigned long long c) {
    unsigned long long d;
    asm("fma.rn.f32x2 %0, %1, %2, %3;" : "=l"(d) : "l"(a), "l"(b), "l"(c));
    return d;
}
__device__ __forceinline__ unsigned long long mul2(
    unsigned long long a, unsigned long long b) {
    unsigned long long d;
    asm("mul.rn.f32x2 %0, %1, %2;" : "=l"(d) : "l"(a), "l"(b));
    return d;
}
__device__ __forceinline__ void unpack2(unsigned long long v, float& lo, float& hi) {
    asm("mov.b64 {%0, %1}, %2;" : "=f"(lo), "=f"(hi) : "l"(v));
}

__global__ __launch_bounds__(NN) void fused_kernel(
    const float* __restrict__ pred,
    const float* __restrict__ target,
    const void*  __restrict__ validp,
    float*       __restrict__ out)
{
    __shared__ __align__(16) unsigned int s_key[NN];  // sorted runs (32/warp)
    __shared__ float s_p[NN];                  // pred by item index
    __shared__ float s_tm[NN];                 // masked time by item index
    __shared__ __align__(16) float s_e2[NN];   // exp(pred), sorted
    __shared__ __align__(16) float s_rz[NN];   // valid ? 1/exp(pred) : 0, sorted
    __shared__ __align__(16) float s_t2[NN];   // masked time, sorted
    __shared__ float s_w0[8];                  // scan warp totals
    __shared__ float s_u0[8], s_u1[8];         // final block-reduce arrays
    __shared__ float s_u2[8];
    __shared__ int   s_vc[8];
    __shared__ unsigned int s_islast;

    const int tid  = threadIdx.x;
    const int lane = tid & 31;
    const int wid  = tid >> 5;
    const int b    = blockIdx.x;
    const int idx  = b * NN + tid;

    // ---- valid_mask dtype detection: warp-local, element SIZE only ----
    const unsigned int w = ((const unsigned int*)validp)[tid];
    unsigned int pat = 0u;
    if ((w == 0x3F803F80u) || (w == 0x00003F80u)) pat |= 1u;          // 2-byte
    else if ((w & 0xFFFFFF00u) != 0u && w != 0x3F800000u) pat |= 4u;  // 1-byte
    const unsigned int wpat = __reduce_or_sync(0xffffffffu, pat);
    bool v_i;
    if (wpat & 1u)      v_i = ((const unsigned short*)validp)[idx] != 0;
    else if (wpat & 4u) v_i = ((const unsigned char*)validp)[idx] != 0;
    else                v_i = ((const unsigned int*)validp)[idx] != 0u;

    const float p_i  = pred[idx];
    const float t_i  = target[idx];
    const float tm_i = v_i ? t_i : -1.0f;

    // unique sortable key: ordered float bits, low 8 bits = item index
    unsigned int u = __float_as_uint(tm_i);
    u ^= (unsigned int)((int)u >> 31) | 0x80000000u;
    const unsigned int key = (u & 0xFFFFFF00u) | (unsigned int)tid;

    s_p[tid]  = p_i;
    s_tm[tid] = tm_i;
    const unsigned int bal = __ballot_sync(0xffffffffu, v_i);
    if (lane == 0) s_vc[wid] = __popc(bal);

    // ---- warp bitonic sort (ascending by lane) of the 32 keys ----
    unsigned int v = key;
    #pragma unroll
    for (int kk = 2; kk <= 32; kk <<= 1) {
        #pragma unroll
        for (int j = kk >> 1; j > 0; j >>= 1) {
            const unsigned int o = __shfl_xor_sync(0xffffffffu, v, j);
            const bool takeMin = (((lane & kk) == 0) == ((lane & j) == 0));
            v = takeMin ? umin(v, o) : umax(v, o);
        }
    }
    s_key[wid * 32 + lane] = v;
    __syncthreads();                                   // B1

    // ---- global rank of v: own run contributes `lane` (keys unique, run
    //      ascending); 7 other runs via branchless lower_bound. The
    //      (w2 == wid) skip is warp-uniform -> divergence-free. ----
    int rank = lane;
    #pragma unroll
    for (int w2 = 0; w2 < 8; w2++) {
        if (w2 != wid) {
            const unsigned int* run = s_key + w2 * 32;
            int c = 0;
            if (run[c + 15] < v) c += 16;
            if (run[c + 7]  < v) c += 8;
            if (run[c + 3]  < v) c += 4;
            if (run[c + 1]  < v) c += 2;
            if (run[c]      < v) c += 1;
            if (run[c]      < v) c += 1;   // fixup (count may be 32)
            rank += c;
        }
    }

    // ---- holder-thread scatter: item i2 = v & 0xFF goes to slot `rank` ----
    {
        const int i2    = (int)(v & 0xFFu);
        const float p2  = s_p[i2];
        const float tm2 = s_tm[i2];
        const float e2  = __expf(p2);
        s_e2[rank] = e2;
        s_rz[rank] = (tm2 < 0.0f) ? 0.0f : __frcp_rn(e2);
        s_t2[rank] = tm2;
    }
    int vcnt = 0;
    #pragma unroll
    for (int k2 = 0; k2 < 8; k2++) vcnt += s_vc[k2];
    const int ninv = NN - vcnt;
    __syncthreads();                                   // B2

    const int   k   = tid;            // sorted slot owned by this thread
    const float E_k = s_e2[k];
    const float T_k = s_t2[k];
    const float bmax = s_t2[NN - 1];

    // ---- den_k = suffix sum of E over [k, 255] ----
    float sfx = E_k;
    #pragma unroll
    for (int o = 1; o < 32; o <<= 1) {
        const float t = __shfl_down_sync(0xffffffffu, sfx, o);
        if (lane + o < 32) sfx += t;
    }
    if (lane == 0) s_w0[wid] = sfx;
    __syncthreads();                                   // B3
    float den = sfx;
    #pragma unroll
    for (int k2 = 7; k2 > 0; k2--) if (k2 > wid) den += s_w0[k2];
    const float invden = 1.0f / den;

    const int qb = k >> 2;       // boundary quad index
    const int kc = k & 3;        // position within boundary quad

    // ---- rank violations over prefix j<k: full quads [0,qb), boundary ----
    const float4* e4 = (const float4*)s_e2;
    const float4* z4 = (const float4*)s_rz;
    float rsA = 0.0f, rsB = 0.0f;
    #pragma unroll 4
    for (int q = 0; q < qb; q++) {
        const float4 E = e4[q];
        const float4 Z = z4[q];
        if (E.x < E_k) rsA += Z.x;
        if (E.y < E_k) rsB += Z.y;
        if (E.z < E_k) rsA += Z.z;
        if (E.w < E_k) rsB += Z.w;
    }
    {   // boundary quad: pairs j = 4*qb + c with c < kc
        const float4 E = e4[qb];
        const float4 Z = z4[qb];
        if (0 < kc && E.x < E_k) rsA += Z.x;
        if (1 < kc && E.y < E_k) rsB += Z.y;
        if (2 < kc && E.z < E_k) rsA += Z.z;
    }
    const float rs = rsA + rsB;

    // ---- pass 2: survival product over strict suffix j>k ----
    // term_j = (1+eps) - E_j/den_k  (clamp provably never fires for j>k)
    const float c1c = 1.0f + EPSF;
    float pdx = 1.0f;
    {   // boundary quad: pairs j = 4*qb + c with c > kc
        const float4 E = e4[qb];
        if (0 > kc) pdx *= fmaf(-E.x, invden, c1c);
        if (1 > kc) pdx *= fmaf(-E.y, invden, c1c);
        if (2 > kc) pdx *= fmaf(-E.z, invden, c1c);
        if (3 > kc) pdx *= fmaf(-E.w, invden, c1c);
    }
    const unsigned long long ninv2 = pack2(-invden, -invden);
    const unsigned long long c1c2  = pack2(c1c, c1c);
    unsigned long long pdA = pack2(1.0f, 1.0f);
    unsigned long long pdB = pdA;
    const ulonglong2* e8 = (const ulonglong2*)s_e2;
    #pragma unroll 4
    for (int q = qb + 1; q < NN / 4; q++) {
        const ulonglong2 E2 = e8[q];
        pdA = mul2(pdA, fma2(E2.x, ninv2, c1c2));
        pdB = mul2(pdB, fma2(E2.y, ninv2, c1c2));
    }
    float a0, a1, b0, b1;
    unpack2(pdA, a0, a1);
    unpack2(pdB, b0, b1);
    const float prod = pdx * ((a0 * a1) * (b0 * b1));

    // ---- finalize per sorted slot ----
    const bool valid_k = (k >= ninv);
    const bool elim = valid_k && (T_k > 0.0f) && (T_k < bmax);
    float loss = 0.0f;
    if (elim)
        loss = __logf(den / (E_k * prod));
    float rankc = valid_k ? E_k * rs : 0.0f;

    // ---- block reduce (loss, rankc) — dedicated arrays, no extra barrier ----
    #pragma unroll
    for (int o = 16; o; o >>= 1) {
        loss  += __shfl_xor_sync(0xffffffffu, loss, o);
        rankc += __shfl_xor_sync(0xffffffffu, rankc, o);
    }
    if (lane == 0) { s_u0[wid] = loss; s_u1[wid] = rankc; }
    __syncthreads();                                   // B4
    if (tid == 0) {
        float tl = 0.0f, tr = 0.0f;
        #pragma unroll
        for (int k2 = 0; k2 < 8; k2++) { tl += s_u0[k2]; tr += s_u1[k2]; }
        const float fv = (float)vcnt;
        const float npairs = 0.5f * fv * (fv - 1.0f);   // C(vcnt,2)
        const float vb = (vcnt >= 2) ? 1.0f : 0.0f;
        g_row_cox[b]  = vb * tl;
        g_row_vb[b]   = vb;
        g_row_rank[b] = tr / fmaxf(npairs, 1.0f);
        __threadfence();
        const unsigned int t = atomicAdd(&g_done, 1u);
        s_islast = (t == (unsigned int)(BB - 1)) ? 1u : 0u;
    }
    __syncthreads();                                   // B5

    // ---- last block: final scalar reduction over 512 rows ----
    if (s_islast) {
        float c  = g_row_cox[tid]  + g_row_cox[tid + NN];
        float v2 = g_row_vb[tid]   + g_row_vb[tid + NN];
        float r  = g_row_rank[tid] + g_row_rank[tid + NN];
        #pragma unroll
        for (int o = 16; o; o >>= 1) {
            c  += __shfl_xor_sync(0xffffffffu, c, o);
            v2 += __shfl_xor_sync(0xffffffffu, v2, o);
            r  += __shfl_xor_sync(0xffffffffu, r, o);
        }
        if (lane == 0) { s_u0[wid] = c; s_u1[wid] = v2; s_u2[wid] = r; }
        __syncthreads();
        if (tid == 0) {
            float C = 0.0f, V = 0.0f, R = 0.0f;
            #pragma unroll
            for (int k2 = 0; k2 < 8; k2++) {
                C += s_u0[k2]; V += s_u1[k2]; R += s_u2[k2];
            }
            out[0] = C / fmaxf(V, 1.0f) + R * (1.0f / (float)BB);
            g_done = 0;   // reset for next graph replay
        }
    }
}

extern "C" void kernel_launch(void* const* d_in, const int* in_sizes, int n_in,
                              void* d_out, int out_size)
{
    const float* pred   = (const float*)d_in[0];
    const float* target = (const float*)d_in[1];
    const void*  valid  = (const void*)d_in[2];
    float*       out    = (float*)d_out;

    fused_kernel<<<BB, NN>>>(pred, target, valid, out);
}